// round 7
// baseline (speedup 1.0000x reference)
#include <cuda_runtime.h>
#include <cuda_bf16.h>

#define N1C 8192
#define N2C 8192
#define BC  2
#define TILE 2048
#define WPB 4                 // warps per block (all share one query set)
#define SLICE (TILE / WPB)    // 512 points per warp per tile
#define QPB 32                // queries per block = one per lane

__device__ __forceinline__ bool kvless(float ad, int ai, float bd, int bi) {
    return ad < bd || (ad == bd && ai < bi);
}

// reference-rounding sum of squares: fl(fl(x*x + y*y) + z*z), squares rounded
__device__ __forceinline__ float sqsum_ref(float x, float y, float z) {
    float xx = __fmul_rn(x, x);
    float yy = __fmul_rn(y, y);
    float zz = __fmul_rn(z, z);
    return __fadd_rn(__fadd_rn(xx, yy), zz);
}

__global__ __launch_bounds__(128) void knn_kernel(
    const float* __restrict__ p1, const float* __restrict__ p2,
    const float* __restrict__ c1, float* __restrict__ out)
{
    __shared__ float4 s[TILE];
    __shared__ float  md[QPB][WPB][3];   // per-warp partial top-3 dists
    __shared__ int    mi[QPB][WPB][3];   // per-warp partial top-3 idxs

    const int b    = blockIdx.y;
    const int lane = threadIdx.x & 31;
    const int warp = threadIdx.x >> 5;
    const int m    = blockIdx.x * QPB + lane;   // query id owned by this lane

    const float* q = p2 + ((size_t)b * N2C + m) * 3;
    const float qx = q[0], qy = q[1], qz = q[2];
    const float nx = -2.0f * qx, ny = -2.0f * qy, nz = -2.0f * qz; // exact
    const float sq2 = sqsum_ref(qx, qy, qz);

    float b0 = 3.4e38f, b1 = 3.4e38f, b2 = 3.4e38f;
    int   i0 = 0, i1 = 0, i2 = 0;
    float tauf = 3.4e38f;  // = b2 - sq2 + eps, refreshed on insert

    const float* pb = p1 + (size_t)b * N1C * 3;

    for (int t0 = 0; t0 < N1C; t0 += TILE) {
        __syncthreads();
        // cooperative tile load: (x, y, z, ||p||^2 in reference rounding)
        for (int i = threadIdx.x; i < TILE; i += blockDim.x) {
            const float* p = pb + (size_t)(t0 + i) * 3;
            float x = p[0], y = p[1], z = p[2];
            s[i] = make_float4(x, y, z, sqsum_ref(x, y, z));
        }
        __syncthreads();

        // this warp scans its 512-point slice; ALL lanes read the SAME
        // point (broadcast LDS) and test it against their own query.
        const float4* sp = s + warp * SLICE;
        const int jb = t0 + warp * SLICE;

        #pragma unroll 8
        for (int k = 0; k < SLICE; ++k) {
            float4 p = sp[k];
            // fast approximate distance (contracted FMAs, minus sq2 term)
            float df = fmaf(nz, p.z, fmaf(ny, p.y, fmaf(nx, p.x, p.w)));
            if (df < tauf) {
                // exact reference-rounded distance:
                //   inner = rn(rn(rn(qx*px)+rn(qy*py))+rn(qz*pz))
                //   d     = rn( rn(sq2+sq1) - 2*inner )
                float m0 = __fmul_rn(qx, p.x);
                float m1 = __fmul_rn(qy, p.y);
                float m2 = __fmul_rn(qz, p.z);
                float inner = __fadd_rn(__fadd_rn(m0, m1), m2);
                float ssum  = __fadd_rn(sq2, p.w);
                float d     = fmaf(-2.0f, inner, ssum);
                if (d < b2) {
                    int j = jb + k;
                    if (d < b1) {
                        b2 = b1; i2 = i1;
                        if (d < b0) { b1 = b0; i1 = i0; b0 = d; i0 = j; }
                        else        { b1 = d;  i1 = j; }
                    } else { b2 = d; i2 = j; }
                    tauf = __fadd_rn(b2, -sq2) + 1e-3f;
                }
            }
        }
    }

    // publish this warp's partial triple for its 32 queries
    md[lane][warp][0] = b0; md[lane][warp][1] = b1; md[lane][warp][2] = b2;
    mi[lane][warp][0] = i0; mi[lane][warp][1] = i1; mi[lane][warp][2] = i2;
    __syncthreads();

    // warp 0 merges the 4 partial triples per query (lane = query) with
    // full lexicographic (d, idx) order -> reference tie-breaking.
    if (warp == 0) {
        float B0 = 3.4e38f, B1 = 3.4e38f, B2 = 3.4e38f;
        int   I0 = 0x7fffffff, I1 = 0x7fffffff, I2 = 0x7fffffff;
        #pragma unroll
        for (int w = 0; w < WPB; ++w) {
            #pragma unroll
            for (int r = 0; r < 3; ++r) {
                float d = md[lane][w][r];
                int   j = mi[lane][w][r];
                if (kvless(d, j, B2, I2)) {
                    if (kvless(d, j, B1, I1)) {
                        B2 = B1; I2 = I1;
                        if (kvless(d, j, B0, I0)) { B1 = B0; I1 = I0; B0 = d; I0 = j; }
                        else                      { B1 = d;  I1 = j; }
                    } else { B2 = d; I2 = j; }
                }
            }
        }

        const float* cb = c1 + (size_t)b * N1C * 3;
        const float* ca = cb + (size_t)I0 * 3;   // rank-0 neighbor
        const float* cc = cb + (size_t)I1 * 3;   // rank-1
        const float* cd = cb + (size_t)I2 * 3;   // rank-2
        float* o = out + ((size_t)b * N2C + m) * 3;
        #pragma unroll
        for (int c = 0; c < 3; c++) {
            // jnp.mean over K: rn(rn(rn(c0+c1)+c2) / 3)
            float ssum = __fadd_rn(__fadd_rn(ca[c], cc[c]), cd[c]);
            o[c] = __fdiv_rn(ssum, 3.0f);
        }
    }
}

extern "C" void kernel_launch(void* const* d_in, const int* in_sizes, int n_in,
                              void* d_out, int out_size) {
    const float* p1 = (const float*)d_in[0];   // points1 [B, N1, 3]
    const float* p2 = (const float*)d_in[1];   // points2 [B, N2, 3]
    const float* c1 = (const float*)d_in[2];   // colors1 [B, N1, 3]
    float* out = (float*)d_out;                // [B, N2, 3] f32

    dim3 grid(N2C / QPB, BC);
    knn_kernel<<<grid, 128>>>(p1, p2, c1, out);
}

// round 8
// speedup vs baseline: 1.1416x; 1.1416x over previous
#include <cuda_runtime.h>
#include <cuda_bf16.h>

#define N1C 8192
#define N2C 8192
#define BC  2
#define TILE 2048
#define WPB 8                 // warps per block (all share one query set)
#define SLICE (TILE / WPB)    // 256 points per warp per tile
#define QPB 32                // queries per block = one per lane
#define RCHUNK 32             // iters between shared-tau refreshes

__device__ __forceinline__ bool kvless(float ad, int ai, float bd, int bi) {
    return ad < bd || (ad == bd && ai < bi);
}

// reference-rounding sum of squares: fl(fl(x*x + y*y) + z*z), squares rounded
__device__ __forceinline__ float sqsum_ref(float x, float y, float z) {
    float xx = __fmul_rn(x, x);
    float yy = __fmul_rn(y, y);
    float zz = __fmul_rn(z, z);
    return __fadd_rn(__fadd_rn(xx, yy), zz);
}

__global__ __launch_bounds__(256) void knn_kernel(
    const float* __restrict__ p1, const float* __restrict__ p2,
    const float* __restrict__ c1, float* __restrict__ out)
{
    __shared__ float4 s[TILE];
    __shared__ float  md[QPB][WPB][3];   // per-warp partial top-3 dists
    __shared__ int    mi[QPB][WPB][3];   // per-warp partial top-3 idxs
    __shared__ float  tau_s[QPB];        // cross-warp shared 3rd-best bound

    const int b    = blockIdx.y;
    const int lane = threadIdx.x & 31;
    const int warp = threadIdx.x >> 5;
    const int m    = blockIdx.x * QPB + lane;   // query id owned by this lane

    volatile float* tau_v = tau_s;

    const float* q = p2 + ((size_t)b * N2C + m) * 3;
    const float qx = q[0], qy = q[1], qz = q[2];
    const float nx = -2.0f * qx, ny = -2.0f * qy, nz = -2.0f * qz; // exact
    const float sq2 = sqsum_ref(qx, qy, qz);

    float b0 = 3.4e38f, b1 = 3.4e38f, b2 = 3.4e38f;
    int   i0 = 0, i1 = 0, i2 = 0;
    float tauf = 3.4e38f;

    if (warp == 0) tau_s[lane] = 3.4e38f;

    const float* pb = p1 + (size_t)b * N1C * 3;

    for (int t0 = 0; t0 < N1C; t0 += TILE) {
        __syncthreads();
        // cooperative tile load: (x, y, z, ||p||^2 in reference rounding)
        for (int i = threadIdx.x; i < TILE; i += blockDim.x) {
            const float* p = pb + (size_t)(t0 + i) * 3;
            float x = p[0], y = p[1], z = p[2];
            s[i] = make_float4(x, y, z, sqsum_ref(x, y, z));
        }
        __syncthreads();

        // this warp scans its 256-point slice; ALL lanes read the SAME
        // point (broadcast LDS) and test it against their own query.
        const float4* sp = s + warp * SLICE;
        const int jb = t0 + warp * SLICE;

        for (int c = 0; c < SLICE / RCHUNK; ++c) {
            // refresh shared threshold (races benign: any published b2 is
            // >= the query's final 3rd-best, so the filter stays safe)
            float t = fminf(tau_v[lane], b2);
            tau_v[lane] = t;
            tauf = __fadd_rn(t, -sq2) + 1e-3f;

            #pragma unroll 8
            for (int k = c * RCHUNK; k < c * RCHUNK + RCHUNK; ++k) {
                float4 p = sp[k];
                // fast approximate distance (contracted FMAs, minus sq2)
                float df = fmaf(nz, p.z, fmaf(ny, p.y, fmaf(nx, p.x, p.w)));
                if (df < tauf) {
                    // exact reference-rounded distance:
                    //   inner = rn(rn(rn(qx*px)+rn(qy*py))+rn(qz*pz))
                    //   d     = rn( rn(sq2+sq1) - 2*inner )
                    float m0 = __fmul_rn(qx, p.x);
                    float m1 = __fmul_rn(qy, p.y);
                    float m2 = __fmul_rn(qz, p.z);
                    float inner = __fadd_rn(__fadd_rn(m0, m1), m2);
                    float ssum  = __fadd_rn(sq2, p.w);
                    float d     = fmaf(-2.0f, inner, ssum);
                    if (d < b2) {
                        int j = jb + k;
                        if (d < b1) {
                            b2 = b1; i2 = i1;
                            if (d < b0) { b1 = b0; i1 = i0; b0 = d; i0 = j; }
                            else        { b1 = d;  i1 = j; }
                        } else { b2 = d; i2 = j; }
                        tauf = fminf(tauf, __fadd_rn(b2, -sq2) + 1e-3f);
                    }
                }
            }
        }
    }

    // publish this warp's partial triple for its 32 queries
    md[lane][warp][0] = b0; md[lane][warp][1] = b1; md[lane][warp][2] = b2;
    mi[lane][warp][0] = i0; mi[lane][warp][1] = i1; mi[lane][warp][2] = i2;
    __syncthreads();

    // warp 0 merges the 8 partial triples per query (lane = query) with
    // full lexicographic (d, idx) order -> reference tie-breaking.
    if (warp == 0) {
        float B0 = 3.4e38f, B1 = 3.4e38f, B2 = 3.4e38f;
        int   I0 = 0x7fffffff, I1 = 0x7fffffff, I2 = 0x7fffffff;
        #pragma unroll
        for (int w = 0; w < WPB; ++w) {
            #pragma unroll
            for (int r = 0; r < 3; ++r) {
                float d = md[lane][w][r];
                int   j = mi[lane][w][r];
                if (kvless(d, j, B2, I2)) {
                    if (kvless(d, j, B1, I1)) {
                        B2 = B1; I2 = I1;
                        if (kvless(d, j, B0, I0)) { B1 = B0; I1 = I0; B0 = d; I0 = j; }
                        else                      { B1 = d;  I1 = j; }
                    } else { B2 = d; I2 = j; }
                }
            }
        }

        const float* cb = c1 + (size_t)b * N1C * 3;
        const float* ca = cb + (size_t)I0 * 3;   // rank-0 neighbor
        const float* cc = cb + (size_t)I1 * 3;   // rank-1
        const float* cd = cb + (size_t)I2 * 3;   // rank-2
        float* o = out + ((size_t)b * N2C + m) * 3;
        #pragma unroll
        for (int c = 0; c < 3; c++) {
            // jnp.mean over K: rn(rn(rn(c0+c1)+c2) / 3)
            float ssum = __fadd_rn(__fadd_rn(ca[c], cc[c]), cd[c]);
            o[c] = __fdiv_rn(ssum, 3.0f);
        }
    }
}

extern "C" void kernel_launch(void* const* d_in, const int* in_sizes, int n_in,
                              void* d_out, int out_size) {
    const float* p1 = (const float*)d_in[0];   // points1 [B, N1, 3]
    const float* p2 = (const float*)d_in[1];   // points2 [B, N2, 3]
    const float* c1 = (const float*)d_in[2];   // colors1 [B, N1, 3]
    float* out = (float*)d_out;                // [B, N2, 3] f32

    dim3 grid(N2C / QPB, BC);
    knn_kernel<<<grid, 256>>>(p1, p2, c1, out);
}